// round 17
// baseline (speedup 1.0000x reference)
#include <cuda_runtime.h>
#include <cstdint>
#include <cstddef>

// Problem constants
#define OSIZE 224
#define NB 64
#define HM 512
#define WMETA 513
#define WMC 512          // image width without metadata column
#define ROWS_PER_BLK 2

// ---------------------------------------------------------------------------
// Threefry-2x32 (JAX-compatible): 20 rounds, key schedule ks2 = k0^k1^parity
// ---------------------------------------------------------------------------
__device__ __forceinline__ void tf2x32(uint32_t k0, uint32_t k1,
                                       uint32_t x0, uint32_t x1,
                                       uint32_t &o0, uint32_t &o1) {
    uint32_t ks2 = k0 ^ k1 ^ 0x1BD11BDAu;
    x0 += k0; x1 += k1;
#define TF_RND(r) { x0 += x1; x1 = (x1 << (r)) | (x1 >> (32 - (r))); x1 ^= x0; }
    TF_RND(13) TF_RND(15) TF_RND(26) TF_RND(6)
    x0 += k1;  x1 += ks2 + 1u;
    TF_RND(17) TF_RND(29) TF_RND(16) TF_RND(24)
    x0 += ks2; x1 += k0 + 2u;
    TF_RND(13) TF_RND(15) TF_RND(26) TF_RND(6)
    x0 += k0;  x1 += k1 + 3u;
    TF_RND(17) TF_RND(29) TF_RND(16) TF_RND(24)
    x0 += k1;  x1 += ks2 + 4u;
    TF_RND(13) TF_RND(15) TF_RND(26) TF_RND(6)
    x0 += ks2; x1 += k0 + 5u;
#undef TF_RND
    o0 = x0; o1 = x1;
}

// Constexpr mirror of tf2x32 (host compile-time evaluation). Returns
// (o1 << 32) | o0. Injection j uses (key[j%3], key[(j+1)%3] + j); rot set A
// for odd j's preceding rounds, B for even — matches the device unroll.
constexpr unsigned long long tf_const(unsigned k0, unsigned k1,
                                      unsigned x0, unsigned x1) {
    unsigned key0 = k0, key1 = k1, key2 = k0 ^ k1 ^ 0x1BD11BDAu;
    unsigned key[3] = {key0, key1, key2};
    unsigned rotA[4] = {13u, 15u, 26u, 6u};
    unsigned rotB[4] = {17u, 29u, 16u, 24u};
    x0 += key[0]; x1 += key[1];
    for (int j = 1; j <= 5; j++) {
        const unsigned* rot = (j % 2) ? rotA : rotB;
        for (int r = 0; r < 4; r++) {
            x0 += x1;
            x1 = (x1 << rot[r]) | (x1 >> (32u - rot[r]));
            x1 ^= x0;
        }
        x0 += key[j % 3];
        x1 += key[(j + 1) % 3] + (unsigned)j;
    }
    return ((unsigned long long)x1 << 32) | (unsigned long long)x0;
}

// Compile-time key table. Partitionable JAX derivations:
//   kparams = tf(key42,(0,1)); kt = tf(kparams,(0,t)); km = tf(kt,(0,m))
//   kflip   = tf(key42,(0,0))
// Entries 0..39 = km for (t = i>>2, m = i&3); entry 40 = kflip.
struct KeyTab { unsigned a[41]; unsigned b[41]; };
constexpr KeyTab build_tab() {
    KeyTab t{};
    unsigned long long kp = tf_const(0u, 42u, 0u, 1u);
    for (int ty = 0; ty < 10; ty++) {
        unsigned long long kt = tf_const((unsigned)kp, (unsigned)(kp >> 32),
                                         0u, (unsigned)ty);
        for (int m = 0; m < 4; m++) {
            unsigned long long km = tf_const((unsigned)kt, (unsigned)(kt >> 32),
                                             0u, (unsigned)m);
            t.a[ty * 4 + m] = (unsigned)km;
            t.b[ty * 4 + m] = (unsigned)(km >> 32);
        }
    }
    unsigned long long kf = tf_const(0u, 42u, 0u, 0u);
    t.a[40] = (unsigned)kf;
    t.b[40] = (unsigned)(kf >> 32);
    return t;
}
__constant__ KeyTab TAB = build_tab();

// bits -> [0,1) float, JAX style: (bits>>9 | 0x3f800000) as float - 1
__device__ __forceinline__ float bits_to_unit(uint32_t bits) {
    return __uint_as_float((bits >> 9) | 0x3F800000u) - 1.0f;
}

// ---------------------------------------------------------------------------
// Single fused kernel. Per-block prologue (cheap, thanks to constexpr keys):
//   lanes 0..39: ONE threefry draw each -> s_u[t][m]; lane 40: flip draw.
//   sync; warp 0 runs the proven try-math + first-valid ballot + fallback;
//   lane 0 publishes packed params to smem; sync; R7-proven resize body.
// Param-path float math uses _rn intrinsics (IEEE RN regardless of flags).
// ---------------------------------------------------------------------------
__global__ void __launch_bounds__(OSIZE)
fused_kernel(const float* __restrict__ x, float* __restrict__ out) {
    __shared__ float s_u[10][4];
    __shared__ int   s_flip;
    __shared__ int   s_prm[4];   // pi, pj, ph, pw|(flip<<16)

    const int tid = threadIdx.x;               // 0..223
    const int oy0 = blockIdx.x * ROWS_PER_BLK; // 0,2,..,222
    const int b   = blockIdx.y;                // 0..63

    // --- draws (one tf each) ---
    if (tid < 40) {
        uint32_t o0, o1;
        tf2x32(TAB.a[tid], TAB.b[tid], 0u, (uint32_t)b, o0, o1);
        s_u[tid >> 2][tid & 3] = bits_to_unit(o0 ^ o1);
    } else if (tid == 40) {
        uint32_t o0, o1;
        tf2x32(TAB.a[40], TAB.b[40], 0u, (uint32_t)b, o0, o1);
        s_flip = bits_to_unit(o0 ^ o1) > 0.5f;
    }
    __syncthreads();

    // --- try-math + selection (warp 0; verbatim proven logic on smem u's) ---
    if (tid < 32) {
        const int lane = tid;
        const unsigned FULL = 0xFFFFFFFFu;
        const int img_stride = 3 * HM * WMETA;
        float Hf = __ldg(x + b * img_stride + 512);
        float Wf = __ldg(x + b * img_stride + HM * WMETA + 512);

        const float lg_lo = -0.22314355131420976f;  // float32(log(0.8))
        const float lg_hi =  0.22314355131420976f;  // float32(log(1.25))

        bool  valid = false;
        float ch = 0.f, cw = 0.f, ri = 0.f, rj = 0.f;

        if (lane < 10) {
            float u1 = s_u[lane][0];
            u1 = fmaxf(0.1f, __fadd_rn(__fmul_rn(u1, 1.0f - 0.1f), 0.1f));
            float u2 = s_u[lane][1];
            u2 = fmaxf(lg_lo, __fadd_rn(__fmul_rn(u2, lg_hi - lg_lo), lg_lo));

            float area = __fmul_rn(Hf, Wf);
            float ta = __fmul_rn(area, u1);
            float aspect = expf(u2);   // libdevice __nv_expf
            cw = rintf(__fsqrt_rn(__fmul_rn(ta, aspect)));
            ch = rintf(__fsqrt_rn(__fdiv_rn(ta, aspect)));

            valid = (cw > 0.0f) && (cw <= Wf) && (ch > 0.0f) && (ch <= Hf);

            float max_i = fmaxf(__fadd_rn(__fsub_rn(Hf, ch), 1.0f), 1.0f);
            float max_j = fmaxf(__fadd_rn(__fsub_rn(Wf, cw), 1.0f), 1.0f);
            float u3 = s_u[lane][2];
            float u4 = s_u[lane][3];
            ri = floorf(__fmul_rn(u3, max_i));
            rj = floorf(__fmul_rn(u4, max_j));
        }

        unsigned vmask = __ballot_sync(FULL, valid) & 0x3FFu;
        int src = vmask ? (__ffs(vmask) - 1) : -1;

        float fh, fw, fi, fj;
        if (src >= 0) {
            fh = __shfl_sync(FULL, ch, src);
            fw = __shfl_sync(FULL, cw, src);
            fi = __shfl_sync(FULL, ri, src);
            fj = __shfl_sync(FULL, rj, src);
        } else {
            float in_ratio = __fdiv_rn(Wf, Hf);
            fw = (in_ratio > 1.25f) ? rintf(__fmul_rn(Hf, 1.25f)) : Wf;
            fh = (in_ratio < 0.8f)  ? rintf(__fdiv_rn(Wf, 0.8f))  : Hf;
            fi = floorf(__fdiv_rn(__fsub_rn(Hf, fh), 2.0f));
            fj = floorf(__fdiv_rn(__fsub_rn(Wf, fw), 2.0f));
        }

        if (lane == 0) {
            s_prm[0] = (int)fi;
            s_prm[1] = (int)fj;
            s_prm[2] = (int)fh;
            s_prm[3] = (int)fw | (s_flip << 16);
        }
    }
    __syncthreads();

    // --- R7-proven resize body ---
    const int ci = s_prm[0], cj = s_prm[1], ch = s_prm[2];
    const int pw = s_prm[3];
    const int cw = pw & 0xFFFF;
    const int flip = pw >> 16;
    const float hf = (float)ch, wf = (float)cw;
    const int ox = tid;

    // x mapping (shared by both rows), IEEE ops so floors match XLA
    float xsv = __fsub_rn(__fdiv_rn(__fmul_rn((float)ox + 0.5f, wf), 224.0f), 0.5f);
    xsv = fminf(fmaxf(xsv, 0.0f), wf - 1.0f);
    float x0f = floorf(xsv);
    float wx = xsv - x0f;
    int x0 = min(max((int)x0f + cj, 0), WMC - 1);
    int xtop = min(max(cj + cw - 1, 0), WMC - 1);
    int x1 = min(max(x0 + 1, 0), xtop);
    if (flip) { x0 = WMC - x0; x1 = WMC - x1; }

    // y mappings for the two rows
    const int ytop = min(max(ci + ch - 1, 0), HM - 1);
    int y0r[ROWS_PER_BLK], y1r[ROWS_PER_BLK];
    float wyr[ROWS_PER_BLK];
#pragma unroll
    for (int r = 0; r < ROWS_PER_BLK; r++) {
        float ysv = __fsub_rn(__fdiv_rn(__fmul_rn((float)(oy0 + r) + 0.5f, hf), 224.0f), 0.5f);
        ysv = fminf(fmaxf(ysv, 0.0f), hf - 1.0f);
        float y0f = floorf(ysv);
        wyr[r] = ysv - y0f;
        int y0 = min(max((int)y0f + ci, 0), HM - 1);
        y0r[r] = y0;
        y1r[r] = min(max(y0 + 1, 0), ytop);
    }

    const int base = b * (3 * HM * WMETA);

    // Front-batched gathers: 2 rows x 3 channels x 4 taps = 24 independent LDGs
    float g00[ROWS_PER_BLK][3], g01[ROWS_PER_BLK][3];
    float g10[ROWS_PER_BLK][3], g11[ROWS_PER_BLK][3];
#pragma unroll
    for (int r = 0; r < ROWS_PER_BLK; r++) {
        const int r0 = base + y0r[r] * WMETA;
        const int r1 = base + y1r[r] * WMETA;
#pragma unroll
        for (int c = 0; c < 3; c++) {
            const int co = c * (HM * WMETA);
            g00[r][c] = __ldg(x + r0 + co + x0);
            g01[r][c] = __ldg(x + r0 + co + x1);
            g10[r][c] = __ldg(x + r1 + co + x0);
            g11[r][c] = __ldg(x + r1 + co + x1);
        }
    }

    const float omwx = 1.0f - wx;
    const int obase = (b * 3 * OSIZE + oy0) * OSIZE + ox;  // row stride OSIZE

#pragma unroll
    for (int r = 0; r < ROWS_PER_BLK; r++) {
        const float wy = wyr[r], omwy = 1.0f - wy;
#pragma unroll
        for (int c = 0; c < 3; c++) {
            float top = omwx * g00[r][c] + wx * g01[r][c];
            float bot = omwx * g10[r][c] + wx * g11[r][c];
            out[obase + c * (OSIZE * OSIZE) + r * OSIZE] = omwy * top + wy * bot;
        }
    }
}

extern "C" void kernel_launch(void* const* d_in, const int* in_sizes, int n_in,
                              void* d_out, int out_size) {
    const float* x = (const float*)d_in[0];
    float* out = (float*)d_out;

    dim3 grid(OSIZE / ROWS_PER_BLK, NB);
    fused_kernel<<<grid, OSIZE>>>(x, out);
}